// round 7
// baseline (speedup 1.0000x reference)
#include <cuda_runtime.h>
#include <math.h>

typedef unsigned long long ull;

// Problem constants
#define BATCH   8
#define SEQ     2048
#define DMODEL  1024
#define DSPACE  64
#define N_QK    512
#define N_V     256
#define N_REL   128
#define N_VAL   32
#define N_TOT   928
#define K_QK    64
#define K_V     32
#define K_REL   16
#define K_VAL   3

#define TPB      128
#define NTHREADS 512
#define NBLOCKS  (BATCH * SEQ / TPB)      // 128, 16 per batch

// Output layout (float32, reference return order)
#define OFF_IDXQK 0
#define OFF_IDXV  (OFF_IDXQK + BATCH*K_QK)
#define OFF_RWQ   (OFF_IDXV  + BATCH*K_V)
#define OFF_RWK   (OFF_RWQ   + BATCH*N_REL)
#define OFF_VW    (OFF_RWK   + BATCH*N_REL)
#define OFF_WQK   (OFF_VW    + BATCH*N_VAL)
#define OFF_WV    (OFF_WQK   + BATCH*N_QK)

// Shared memory map (bytes)
// U region [0, 131584):
//   GEMM1 phase: XsP ull[64tp][129] (66048) | WsD ull[128d][64col] dup-packed at 66048 (65536)
//   aliased by: GEMM2 embS float[64][<=512] (<=131072)
//   aliased by: GEMM1 exchange xbuf ull[64tp][4ks][64col] (131072)
//   aliased by: per-slice wpart float[<=32][<=512] (<=32768)
//   aliased by: finalize sws/flag
#define SM_HSP2  131584     // HsP2: ull[128tok][65] dup-packed H (66560)
#define SM_WL    198144     // w_local float[928]
#define SM_IMP   201856     // impS float[128]
#define SM_PART  202368     // partS float[128]
#define SM_ALPHA 202880     // alphaS float[128]
#define SM_FLAG  203392     // int
#define SM_BIAS  203520     // float[64]
#define SMEM_BYTES 203776

#define XSP_STRIDE 129      // ull
#define HSP2_STRIDE 65      // ull

// device scratch (no allocation allowed)
__device__ float g_embT[DSPACE * N_TOT];        // normalized emb transposed [d][n]
__device__ float g_wpart[NBLOCKS][N_TOT];       // per-block partial w
__device__ int   g_cnt[BATCH];                  // completion counters

// ---------------- f32x2 helpers ----------------
__device__ __forceinline__ ull d_pack(float x, float y) {
    ull r; asm("mov.b64 %0, {%1, %2};" : "=l"(r) : "f"(x), "f"(y)); return r;
}
__device__ __forceinline__ ull d_dup(float x) {
    ull r; asm("mov.b64 %0, {%1, %1};" : "=l"(r) : "f"(x)); return r;
}
__device__ __forceinline__ void d_unpack(ull v, float& x, float& y) {
    asm("mov.b64 {%0, %1}, %2;" : "=f"(x), "=f"(y) : "l"(v));
}
__device__ __forceinline__ ull d_fma2(ull a, ull b, ull c) {
    ull d; asm("fma.rn.f32x2 %0, %1, %2, %3;" : "=l"(d) : "l"(a), "l"(b), "l"(c)); return d;
}
__device__ __forceinline__ ull d_add2(ull a, ull b) {
    ull d; asm("add.rn.f32x2 %0, %1, %2;" : "=l"(d) : "l"(a), "l"(b)); return d;
}

// ---------------- prep: normalize emb (transposed) + reset counters ----------------
__global__ void prep_kernel(const float* __restrict__ emb) {
    int r = blockIdx.x;     // neuron 0..927
    int t = threadIdx.x;    // dim 0..63
    if (r == 0 && t < BATCH) g_cnt[t] = 0;
    __shared__ float s[64];
    float v = emb[r * DSPACE + t];
    s[t] = v * v;
    __syncthreads();
    #pragma unroll
    for (int o = 32; o > 0; o >>= 1) {
        if (t < o) s[t] += s[t + o];
        __syncthreads();
    }
    float norm = sqrtf(s[0]);
    g_embT[t * N_TOT + r] = v / norm;
}

// ---------------- GEMM2 + softmax + routed-weight slice ----------------
// Tile: 4 tokens x 16 neurons, neurons packed in f32x2 pairs (natural emb layout),
// tokens dup-packed in HsP2 -> inner loop has zero MOVs.
template<int N, int LO>
__device__ __forceinline__ void do_slice(char* sm, int tid) {
    float* embS   = (float*)sm;
    ull*   HsP2   = (ull*)(sm + SM_HSP2);
    float* w_local= (float*)(sm + SM_WL);
    float* impS   = (float*)(sm + SM_IMP);
    float* partS  = (float*)(sm + SM_PART);
    float* alphaS = (float*)(sm + SM_ALPHA);
    float* wpartF = (float*)sm;                       // aliases U after reads done

    constexpr int NQ2  = N / 16;                      // threads along n
    constexpr int LNQ2 = (NQ2==32)?5:(NQ2==16)?4:(NQ2==8)?3:1;
    constexpr int G2   = NTHREADS / NQ2;
    constexpr int TG2  = (4*G2 > TPB) ? TPB : 4*G2;   // tokens per pass
    constexpr int AG2  = TG2 / 4;                     // active groups
    constexpr int N4   = N / 4;

    const int nq2 = tid & (NQ2 - 1);
    const int q2  = tid >> LNQ2;
    const bool active = (q2 < AG2);

    __syncthreads();
    for (int i = tid; i < 64 * N4; i += NTHREADS) {
        int d = i / N4, c = i - d * N4;
        ((float4*)embS)[i] = *(const float4*)(g_embT + (size_t)d * N_TOT + LO + c * 4);
    }
    __syncthreads();

    ull wacc2[8];
    #pragma unroll
    for (int j = 0; j < 8; j++) wacc2[j] = 0ull;

    for (int t0 = 0; t0 < TPB; t0 += TG2) {
        ull acc[4][8];
        if (active) {
            #pragma unroll
            for (int u = 0; u < 4; u++)
                #pragma unroll
                for (int j = 0; j < 8; j++) acc[u][j] = 0ull;

            const ull* hbase = HsP2 + (size_t)(t0 + q2 * 4) * HSP2_STRIDE;
            const char* ebase = (const char*)(embS + nq2 * 4);
            #pragma unroll 2
            for (int d = 0; d < DSPACE; d++) {
                // b: 4x LDS.128, natural f32x2 neuron pairs, 16B lane stride
                ulonglong2 b0 = *(const ulonglong2*)(ebase + (size_t)(d*N + 0*N4) * 4);
                ulonglong2 b1 = *(const ulonglong2*)(ebase + (size_t)(d*N + 1*N4) * 4);
                ulonglong2 b2 = *(const ulonglong2*)(ebase + (size_t)(d*N + 2*N4) * 4);
                ulonglong2 b3 = *(const ulonglong2*)(ebase + (size_t)(d*N + 3*N4) * 4);
                // a: 4x LDS.64 dup-packed tokens
                ull a0 = hbase[d];
                ull a1 = hbase[HSP2_STRIDE + d];
                ull a2 = hbase[2*HSP2_STRIDE + d];
                ull a3 = hbase[3*HSP2_STRIDE + d];
                #pragma unroll
                for (int u = 0; u < 4; u++) {
                    ull a = (u==0)?a0:(u==1)?a1:(u==2)?a2:a3;
                    acc[u][0] = d_fma2(a, b0.x, acc[u][0]);
                    acc[u][1] = d_fma2(a, b0.y, acc[u][1]);
                    acc[u][2] = d_fma2(a, b1.x, acc[u][2]);
                    acc[u][3] = d_fma2(a, b1.y, acc[u][3]);
                    acc[u][4] = d_fma2(a, b2.x, acc[u][4]);
                    acc[u][5] = d_fma2(a, b2.y, acc[u][5]);
                    acc[u][6] = d_fma2(a, b3.x, acc[u][6]);
                    acc[u][7] = d_fma2(a, b3.y, acc[u][7]);
                }
            }
            // exp in place + per-token sums (packed adds)
            float ps[4];
            #pragma unroll
            for (int u = 0; u < 4; u++) {
                #pragma unroll
                for (int j = 0; j < 8; j++) {
                    float lo, hi;
                    d_unpack(acc[u][j], lo, hi);
                    acc[u][j] = d_pack(__expf(lo), __expf(hi));
                }
                ull s01 = d_add2(acc[u][0], acc[u][1]);
                ull s23 = d_add2(acc[u][2], acc[u][3]);
                ull s45 = d_add2(acc[u][4], acc[u][5]);
                ull s67 = d_add2(acc[u][6], acc[u][7]);
                ull sA  = d_add2(d_add2(s01, s23), d_add2(s45, s67));
                float lo, hi; d_unpack(sA, lo, hi);
                ps[u] = lo + hi;
            }
            #pragma unroll
            for (int u = 0; u < 4; u++)
                #pragma unroll
                for (int o = NQ2 >> 1; o > 0; o >>= 1)
                    ps[u] += __shfl_xor_sync(0xffffffffu, ps[u], o);
            if (nq2 == 0) {
                #pragma unroll
                for (int u = 0; u < 4; u++) partS[q2*4 + u] = ps[u];
            }
        }
        __syncthreads();
        if (tid < TG2) alphaS[tid] = impS[t0 + tid] / partS[tid];
        __syncthreads();
        if (active) {
            #pragma unroll
            for (int u = 0; u < 4; u++) {
                ull al = d_dup(alphaS[q2*4 + u]);
                #pragma unroll
                for (int j = 0; j < 8; j++)
                    wacc2[j] = d_fma2(al, acc[u][j], wacc2[j]);
            }
        }
    }
    // store per-group partials into U (embS reads are all complete)
    if (active) {
        #pragma unroll
        for (int g = 0; g < 4; g++)
            #pragma unroll
            for (int p = 0; p < 2; p++)
                *(ull*)(wpartF + (size_t)q2 * N + g * N4 + nq2 * 4 + 2 * p) = wacc2[g*2 + p];
    }
    __syncthreads();
    for (int n = tid; n < N; n += NTHREADS) {
        float s = 0.0f;
        #pragma unroll
        for (int g = 0; g < AG2; g++) s += wpartF[(size_t)g * N + n];
        w_local[LO + n] = s;
    }
    __syncthreads();
}

// ---------------- finalize helpers ----------------
template<int NN, int KK>
__device__ __forceinline__ void topk_flags(const float* ws, int* flag, int tid) {
    for (int i = tid; i < NN; i += NTHREADS) {
        float wi = ws[i]; int r = 0;
        #pragma unroll 16
        for (int j = 0; j < NN; j++) {
            float wj = ws[j];
            r += (wj > wi) || (wj == wi && j < i);
        }
        flag[i] = (r < KK) ? 1 : 0;
    }
}

// ---------------- main fused kernel ----------------
__global__ void __launch_bounds__(NTHREADS, 1)
main_kernel(const float* __restrict__ x, const float* __restrict__ imp,
            const float* __restrict__ Wm, const float* __restrict__ bias,
            float* __restrict__ out)
{
    extern __shared__ char sm[];
    ull*   XsP    = (ull*)sm;                        // [64tp][129]
    ull*   WsD    = (ull*)(sm + 66048);              // [128d][64col] dup pairs
    ull*   xbuf   = (ull*)sm;                        // exchange (aliases)
    ull*   HsP2   = (ull*)(sm + SM_HSP2);            // [128tok][65] dup pairs
    float* w_local= (float*)(sm + SM_WL);
    float* impS   = (float*)(sm + SM_IMP);
    float* biasS  = (float*)(sm + SM_BIAS);

    const int tid = threadIdx.x;
    const int bb  = blockIdx.x >> 4;
    const int loc = blockIdx.x & 15;
    const int s0  = loc * TPB;

    if (tid < TPB) impS[tid] = imp[bb * SEQ + s0 + tid];
    if (tid < DSPACE) biasS[tid] = bias[tid];

    // ---- GEMM1: H[128][64] = X[128][1024] @ W[1024][64] + b ----
    // 512 threads = ks(2b) | tg(4b) | cg(3b); k-split 4, tiles 8tok x 8col
    // thread cols: {16g + 2cg + p : g=0..3, p=0..1}
    const int cg = tid & 7;
    const int tg = (tid >> 3) & 15;  // token pairs tg*4 .. tg*4+3
    const int ks = tid >> 7;         // d-quarter

    ull acc[4][8];
    #pragma unroll
    for (int u = 0; u < 4; u++)
        #pragma unroll
        for (int j = 0; j < 8; j++) acc[u][j] = 0ull;

    const float4* Xg = (const float4*)(x + (size_t)(bb * SEQ + s0) * DMODEL);

    for (int p = 0; p < 8; p++) {
        __syncthreads();
        // XsP: slot = dq + 32c holds logical d = dq*4 + c; STS lane-consecutive
        for (int i = tid; i < 64 * 32; i += NTHREADS) {
            int tp = i >> 5, dq = i & 31;
            float4 fa = Xg[(size_t)(2*tp)   * 256 + p*32 + dq];
            float4 fb = Xg[(size_t)(2*tp+1) * 256 + p*32 + dq];
            ull* dst = XsP + (size_t)tp * XSP_STRIDE + dq;
            dst[0]  = d_pack(fa.x, fb.x);
            dst[32] = d_pack(fa.y, fb.y);
            dst[64] = d_pack(fa.z, fb.z);
            dst[96] = d_pack(fa.w, fb.w);
        }
        // WsD: dup-packed W chunk [128d][64col]
        {
            const float4* Wg = (const float4*)(Wm + (size_t)p * 128 * DSPACE);
            for (int i = tid; i < 2048; i += NTHREADS) {
                float4 w = Wg[i];
                int d = i >> 4, c = (i & 15) * 4;
                ull* dst = WsD + (size_t)d * 64 + c;
                dst[0] = d_dup(w.x);
                dst[1] = d_dup(w.y);
                dst[2] = d_dup(w.z);
                dst[3] = d_dup(w.w);
            }
        }
        __syncthreads();

        const ull* xrow = XsP + (size_t)(tg * 4) * XSP_STRIDE;
        #pragma unroll 2
        for (int i = 0; i < 32; i++) {
            const int slot = ks * 32 + i;
            const int d    = i * 4 + ks;
            const ull* wrow = WsD + (size_t)d * 64 + 2 * cg;
            ulonglong2 b0 = *(const ulonglong2*)(wrow);       // cols 2cg, 2cg+1
            ulonglong2 b1 = *(const ulonglong2*)(wrow + 16);  // cols 16+2cg, +1
            ulonglong2 b2 = *(const ulonglong2*)(wrow + 32);
            ulonglong2 b3 = *(const ulonglong2*)(wrow + 48);
            ull a0 = xrow[slot];
            ull a1 = xrow[XSP_STRIDE + slot];
            ull a2 = xrow[2*XSP_STRIDE + slot];
            ull a3 = xrow[3*XSP_STRIDE + slot];
            #pragma unroll
            for (int u = 0; u < 4; u++) {
                ull a = (u==0)?a0:(u==1)?a1:(u==2)?a2:a3;
                acc[u][0] = d_fma2(a, b0.x, acc[u][0]);
                acc[u][1] = d_fma2(a, b0.y, acc[u][1]);
                acc[u][2] = d_fma2(a, b1.x, acc[u][2]);
                acc[u][3] = d_fma2(a, b1.y, acc[u][3]);
                acc[u][4] = d_fma2(a, b2.x, acc[u][4]);
                acc[u][5] = d_fma2(a, b2.y, acc[u][5]);
                acc[u][6] = d_fma2(a, b3.x, acc[u][6]);
                acc[u][7] = d_fma2(a, b3.y, acc[u][7]);
            }
        }
    }
    // ---- k-split exchange: xbuf[tp][ks][col] (aliases XsP/WsD) ----
    __syncthreads();
    #pragma unroll
    for (int u = 0; u < 4; u++) {
        const int tp = tg * 4 + u;
        #pragma unroll
        for (int g = 0; g < 4; g++)
            #pragma unroll
            for (int pp = 0; pp < 2; pp++) {
                int col = 16*g + 2*cg + pp;
                xbuf[(size_t)tp * 256 + ks * 64 + col] = acc[u][g*2 + pp];
            }
    }
    __syncthreads();
    // reduce 4 partials + bias -> HsP2 dup-packed per token
    #pragma unroll
    for (int k = 0; k < 8; k++) {
        int L = tid * 8 + k;            // 0..4095
        int tp = L >> 6, col = L & 63;
        ull s = d_add2(d_add2(xbuf[(size_t)tp*256 + col],
                              xbuf[(size_t)tp*256 + 64 + col]),
                       d_add2(xbuf[(size_t)tp*256 + 128 + col],
                              xbuf[(size_t)tp*256 + 192 + col]));
        float h0, h1; d_unpack(s, h0, h1);
        float bv = biasS[col];
        HsP2[(size_t)(2*tp)   * HSP2_STRIDE + col] = d_dup(h0 + bv);
        HsP2[(size_t)(2*tp+1) * HSP2_STRIDE + col] = d_dup(h1 + bv);
    }

    // ---- GEMM2 + softmax + routing per slice ----
    do_slice<N_QK, 0>(sm, tid);
    do_slice<N_V,  N_QK>(sm, tid);
    do_slice<N_REL, N_QK + N_V>(sm, tid);
    do_slice<N_VAL, N_QK + N_V + N_REL>(sm, tid);

    for (int i = tid; i < N_TOT; i += NTHREADS)
        g_wpart[blockIdx.x][i] = w_local[i];

    // ---- completion counter: last block of this batch finalizes ----
    int* lastFlag = (int*)(sm + SM_FLAG);
    __threadfence();
    if (tid == 0) {
        int old = atomicAdd(&g_cnt[bb], 1);
        *lastFlag = (old == 15);
    }
    __syncthreads();
    if (!*lastFlag) return;

    // finalize: deterministic sum of the 16 partials, then top-k tasks
    float* sws  = (float*)sm;                 // [928]
    int*   flag = (int*)(sm + 4096);          // [512]
    for (int n = tid; n < N_TOT; n += NTHREADS) {
        float s = 0.0f;
        #pragma unroll
        for (int l = 0; l < 16; l++) s += g_wpart[bb * 16 + l][n];
        sws[n] = s;
    }
    __syncthreads();

    // raw w copies
    for (int i = tid; i < N_QK; i += NTHREADS) out[OFF_WQK + bb * N_QK + i] = sws[i];
    for (int i = tid; i < N_V;  i += NTHREADS) out[OFF_WV  + bb * N_V  + i] = sws[N_QK + i];

    // task 1: qk top-64 indices
    topk_flags<N_QK, K_QK>(sws, flag, tid);
    __syncthreads();
    for (int i = tid; i < N_QK; i += NTHREADS) {
        if (flag[i]) {
            int pos = 0;
            for (int j = 0; j < i; j++) pos += flag[j];
            out[OFF_IDXQK + bb * K_QK + pos] = (float)i;
        }
    }
    __syncthreads();
    // task 2: v top-32 indices
    topk_flags<N_V, K_V>(sws + N_QK, flag, tid);
    __syncthreads();
    for (int i = tid; i < N_V; i += NTHREADS) {
        if (flag[i]) {
            int pos = 0;
            for (int j = 0; j < i; j++) pos += flag[j];
            out[OFF_IDXV + bb * K_V + pos] = (float)i;
        }
    }
    __syncthreads();
    // task 3: rel sparsify top-16 (rw_Q == rw_K)
    topk_flags<N_REL, K_REL>(sws + N_QK + N_V, flag, tid);
    __syncthreads();
    for (int i = tid; i < N_REL; i += NTHREADS) {
        float v = flag[i] ? sws[N_QK + N_V + i] : 0.0f;
        out[OFF_RWQ + bb * N_REL + i] = v;
        out[OFF_RWK + bb * N_REL + i] = v;
    }
    __syncthreads();
    // task 4: val sparsify top-3
    topk_flags<N_VAL, K_VAL>(sws + N_QK + N_V + N_REL, flag, tid);
    __syncthreads();
    for (int i = tid; i < N_VAL; i += NTHREADS)
        out[OFF_VW + bb * N_VAL + i] = flag[i] ? sws[N_QK + N_V + N_REL + i] : 0.0f;
}

extern "C" void kernel_launch(void* const* d_in, const int* in_sizes, int n_in,
                              void* d_out, int out_size) {
    const float* x    = (const float*)d_in[0];
    const float* imp  = (const float*)d_in[1];
    const float* Wm   = (const float*)d_in[2];
    const float* bias = (const float*)d_in[3];
    const float* emb  = (const float*)d_in[4];
    float* out = (float*)d_out;

    cudaFuncSetAttribute(main_kernel, cudaFuncAttributeMaxDynamicSharedMemorySize, SMEM_BYTES);

    prep_kernel<<<N_TOT, 64>>>(emb);
    main_kernel<<<NBLOCKS, NTHREADS, SMEM_BYTES>>>(x, imp, Wm, bias, out);
}

// round 8
// speedup vs baseline: 1.0426x; 1.0426x over previous
#include <cuda_runtime.h>
#include <math.h>

typedef unsigned long long ull;

// Problem constants
#define BATCH   8
#define SEQ     2048
#define DMODEL  1024
#define DSPACE  64
#define N_QK    512
#define N_V     256
#define N_REL   128
#define N_VAL   32
#define N_TOT   928
#define K_QK    64
#define K_V     32
#define K_REL   16
#define K_VAL   3

#define TPB      128
#define NTHREADS 512
#define NBLOCKS  (BATCH * SEQ / TPB)      // 128, 16 per batch

// Output layout (float32, reference return order)
#define OFF_IDXQK 0
#define OFF_IDXV  (OFF_IDXQK + BATCH*K_QK)
#define OFF_RWQ   (OFF_IDXV  + BATCH*K_V)
#define OFF_RWK   (OFF_RWQ   + BATCH*N_REL)
#define OFF_VW    (OFF_RWK   + BATCH*N_REL)
#define OFF_WQK   (OFF_VW    + BATCH*N_VAL)
#define OFF_WV    (OFF_WQK   + BATCH*N_QK)

// Shared memory map (bytes)
// U region [0, 131584):
//   GEMM1: bufXa ull[64tp][65] @0 (33280) | bufWa float[64d][64] @33280 (16384)
//          bufXb @49664 (33280)          | bufWb @82944 (16384)  -> end 99328
//   aliased by: xbuf ull[64tp][4ks][64col] (131072)
//   aliased by: embS float[64][<=512] (<=131072)
//   aliased by: per-slice wpart, finalize sws/flag
#define SM_BXA   0
#define SM_BWA   33280
#define SM_BXB   49664
#define SM_BWB   82944
#define SM_HSP2  131584     // HsP2: ull[128tok][65] dup-packed H (66560)
#define SM_WL    198144     // w_local float[928]
#define SM_IMP   201856     // impS float[128]
#define SM_PART  202368     // partS float[128]
#define SM_ALPHA 202880     // alphaS float[128]
#define SM_FLAG  203392     // int
#define SM_BIAS  203520     // float[64]
#define SMEM_BYTES 203776

#define XSP_STRIDE 65       // ull (64 slots + pad)
#define HSP2_STRIDE 65      // ull

// device scratch (no allocation allowed)
__device__ float g_embT[DSPACE * N_TOT];        // normalized emb transposed [d][n]
__device__ float g_wpart[NBLOCKS][N_TOT];       // per-block partial w
__device__ int   g_cnt[BATCH];                  // completion counters

// ---------------- f32x2 helpers ----------------
__device__ __forceinline__ ull d_pack(float x, float y) {
    ull r; asm("mov.b64 %0, {%1, %2};" : "=l"(r) : "f"(x), "f"(y)); return r;
}
__device__ __forceinline__ ull d_dup(float x) {
    ull r; asm("mov.b64 %0, {%1, %1};" : "=l"(r) : "f"(x)); return r;
}
__device__ __forceinline__ void d_unpack(ull v, float& x, float& y) {
    asm("mov.b64 {%0, %1}, %2;" : "=f"(x), "=f"(y) : "l"(v));
}
__device__ __forceinline__ ull d_fma2(ull a, ull b, ull c) {
    ull d; asm("fma.rn.f32x2 %0, %1, %2, %3;" : "=l"(d) : "l"(a), "l"(b), "l"(c)); return d;
}
__device__ __forceinline__ ull d_add2(ull a, ull b) {
    ull d; asm("add.rn.f32x2 %0, %1, %2;" : "=l"(d) : "l"(a), "l"(b)); return d;
}

// ---------------- prep: normalize emb (transposed) + reset counters ----------------
__global__ void prep_kernel(const float* __restrict__ emb) {
    int r = blockIdx.x;     // neuron 0..927
    int t = threadIdx.x;    // dim 0..63
    if (r == 0 && t < BATCH) g_cnt[t] = 0;
    __shared__ float s[64];
    float v = emb[r * DSPACE + t];
    s[t] = v * v;
    __syncthreads();
    #pragma unroll
    for (int o = 32; o > 0; o >>= 1) {
        if (t < o) s[t] += s[t + o];
        __syncthreads();
    }
    float norm = sqrtf(s[0]);
    g_embT[t * N_TOT + r] = v / norm;
}

// ---------------- GEMM2 + softmax + routed-weight slice (zero-MOV inner loop) ----------------
template<int N, int LO>
__device__ __forceinline__ void do_slice(char* sm, int tid) {
    float* embS   = (float*)sm;
    ull*   HsP2   = (ull*)(sm + SM_HSP2);
    float* w_local= (float*)(sm + SM_WL);
    float* impS   = (float*)(sm + SM_IMP);
    float* partS  = (float*)(sm + SM_PART);
    float* alphaS = (float*)(sm + SM_ALPHA);
    float* wpartF = (float*)sm;                       // aliases U after reads done

    constexpr int NQ2  = N / 16;                      // threads along n
    constexpr int LNQ2 = (NQ2==32)?5:(NQ2==16)?4:(NQ2==8)?3:1;
    constexpr int G2   = NTHREADS / NQ2;
    constexpr int TG2  = (4*G2 > TPB) ? TPB : 4*G2;   // tokens per pass
    constexpr int AG2  = TG2 / 4;                     // active groups
    constexpr int N4   = N / 4;

    const int nq2 = tid & (NQ2 - 1);
    const int q2  = tid >> LNQ2;
    const bool active = (q2 < AG2);

    __syncthreads();
    for (int i = tid; i < 64 * N4; i += NTHREADS) {
        int d = i / N4, c = i - d * N4;
        ((float4*)embS)[i] = *(const float4*)(g_embT + (size_t)d * N_TOT + LO + c * 4);
    }
    __syncthreads();

    ull wacc2[8];
    #pragma unroll
    for (int j = 0; j < 8; j++) wacc2[j] = 0ull;

    for (int t0 = 0; t0 < TPB; t0 += TG2) {
        ull acc[4][8];
        if (active) {
            #pragma unroll
            for (int u = 0; u < 4; u++)
                #pragma unroll
                for (int j = 0; j < 8; j++) acc[u][j] = 0ull;

            const ull* hbase = HsP2 + (size_t)(t0 + q2 * 4) * HSP2_STRIDE;
            const char* ebase = (const char*)(embS + nq2 * 4);
            #pragma unroll 2
            for (int d = 0; d < DSPACE; d++) {
                ulonglong2 b0 = *(const ulonglong2*)(ebase + (size_t)(d*N + 0*N4) * 4);
                ulonglong2 b1 = *(const ulonglong2*)(ebase + (size_t)(d*N + 1*N4) * 4);
                ulonglong2 b2 = *(const ulonglong2*)(ebase + (size_t)(d*N + 2*N4) * 4);
                ulonglong2 b3 = *(const ulonglong2*)(ebase + (size_t)(d*N + 3*N4) * 4);
                ull a0 = hbase[d];
                ull a1 = hbase[HSP2_STRIDE + d];
                ull a2 = hbase[2*HSP2_STRIDE + d];
                ull a3 = hbase[3*HSP2_STRIDE + d];
                #pragma unroll
                for (int u = 0; u < 4; u++) {
                    ull a = (u==0)?a0:(u==1)?a1:(u==2)?a2:a3;
                    acc[u][0] = d_fma2(a, b0.x, acc[u][0]);
                    acc[u][1] = d_fma2(a, b0.y, acc[u][1]);
                    acc[u][2] = d_fma2(a, b1.x, acc[u][2]);
                    acc[u][3] = d_fma2(a, b1.y, acc[u][3]);
                    acc[u][4] = d_fma2(a, b2.x, acc[u][4]);
                    acc[u][5] = d_fma2(a, b2.y, acc[u][5]);
                    acc[u][6] = d_fma2(a, b3.x, acc[u][6]);
                    acc[u][7] = d_fma2(a, b3.y, acc[u][7]);
                }
            }
            // exp in place + per-token sums (packed adds)
            float ps[4];
            #pragma unroll
            for (int u = 0; u < 4; u++) {
                #pragma unroll
                for (int j = 0; j < 8; j++) {
                    float lo, hi;
                    d_unpack(acc[u][j], lo, hi);
                    acc[u][j] = d_pack(__expf(lo), __expf(hi));
                }
                ull s01 = d_add2(acc[u][0], acc[u][1]);
                ull s23 = d_add2(acc[u][2], acc[u][3]);
                ull s45 = d_add2(acc[u][4], acc[u][5]);
                ull s67 = d_add2(acc[u][6], acc[u][7]);
                ull sA  = d_add2(d_add2(s01, s23), d_add2(s45, s67));
                float lo, hi; d_unpack(sA, lo, hi);
                ps[u] = lo + hi;
            }
            #pragma unroll
            for (int u = 0; u < 4; u++)
                #pragma unroll
                for (int o = NQ2 >> 1; o > 0; o >>= 1)
                    ps[u] += __shfl_xor_sync(0xffffffffu, ps[u], o);
            if (nq2 == 0) {
                #pragma unroll
                for (int u = 0; u < 4; u++) partS[q2*4 + u] = ps[u];
            }
        }
        __syncthreads();
        if (tid < TG2) alphaS[tid] = impS[t0 + tid] / partS[tid];
        __syncthreads();
        if (active) {
            #pragma unroll
            for (int u = 0; u < 4; u++) {
                ull al = d_dup(alphaS[q2*4 + u]);
                #pragma unroll
                for (int j = 0; j < 8; j++)
                    wacc2[j] = d_fma2(al, acc[u][j], wacc2[j]);
            }
        }
    }
    // store per-group partials into U (embS reads are all complete)
    if (active) {
        #pragma unroll
        for (int g = 0; g < 4; g++)
            #pragma unroll
            for (int p = 0; p < 2; p++)
                *(ull*)(wpartF + (size_t)q2 * N + g * N4 + nq2 * 4 + 2 * p) = wacc2[g*2 + p];
    }
    __syncthreads();
    for (int n = tid; n < N; n += NTHREADS) {
        float s = 0.0f;
        #pragma unroll
        for (int g = 0; g < AG2; g++) s += wpartF[(size_t)g * N + n];
        w_local[LO + n] = s;
    }
    __syncthreads();
}

// ---------------- finalize helpers ----------------
template<int NN, int KK>
__device__ __forceinline__ void topk_flags(const float* ws, int* flag, int tid) {
    for (int i = tid; i < NN; i += NTHREADS) {
        float wi = ws[i]; int r = 0;
        #pragma unroll 16
        for (int j = 0; j < NN; j++) {
            float wj = ws[j];
            r += (wj > wi) || (wj == wi && j < i);
        }
        flag[i] = (r < KK) ? 1 : 0;
    }
}

// ---------------- GEMM1 chunk compute (64 d), R6-style (float4 W + reg dups) ----------------
__device__ __forceinline__ void g1_compute(const ull* __restrict__ bx,
                                           const float* __restrict__ bw,
                                           int cg, int tg, int ks, ull acc[4][8]) {
    const ull* xrow = bx + (size_t)(tg * 4) * XSP_STRIDE;
    const float4* Ws4 = (const float4*)bw;
    #pragma unroll 4
    for (int i = 0; i < 16; i++) {
        const int slot = ks * 16 + i;      // holds logical d = i*4 + ks
        const int d    = i * 4 + ks;
        float4 b0 = Ws4[d * 16 + cg];      // cols 4cg..4cg+3
        float4 b1 = Ws4[d * 16 + 8 + cg];  // cols 32+4cg..+3
        ull bd[8];
        bd[0]=d_dup(b0.x); bd[1]=d_dup(b0.y); bd[2]=d_dup(b0.z); bd[3]=d_dup(b0.w);
        bd[4]=d_dup(b1.x); bd[5]=d_dup(b1.y); bd[6]=d_dup(b1.z); bd[7]=d_dup(b1.w);
        ull a0 = bx ? xrow[slot] : 0;      // (bx always non-null; keeps ptxas honest)
        a0 = xrow[slot];
        ull a1 = xrow[XSP_STRIDE + slot];
        ull a2 = xrow[2*XSP_STRIDE + slot];
        ull a3 = xrow[3*XSP_STRIDE + slot];
        #pragma unroll
        for (int j = 0; j < 8; j++) {
            acc[0][j] = d_fma2(a0, bd[j], acc[0][j]);
            acc[1][j] = d_fma2(a1, bd[j], acc[1][j]);
            acc[2][j] = d_fma2(a2, bd[j], acc[2][j]);
            acc[3][j] = d_fma2(a3, bd[j], acc[3][j]);
        }
    }
}

// ---------------- main fused kernel ----------------
__global__ void __launch_bounds__(NTHREADS, 1)
main_kernel(const float* __restrict__ x, const float* __restrict__ imp,
            const float* __restrict__ Wm, const float* __restrict__ bias,
            float* __restrict__ out)
{
    extern __shared__ char sm[];
    ull*   bxA    = (ull*)(sm + SM_BXA);
    float* bwA    = (float*)(sm + SM_BWA);
    ull*   bxB    = (ull*)(sm + SM_BXB);
    float* bwB    = (float*)(sm + SM_BWB);
    ull*   xbuf   = (ull*)sm;                        // exchange (aliases buffers)
    ull*   HsP2   = (ull*)(sm + SM_HSP2);
    float* w_local= (float*)(sm + SM_WL);
    float* impS   = (float*)(sm + SM_IMP);
    float* biasS  = (float*)(sm + SM_BIAS);

    const int tid = threadIdx.x;
    const int bb  = blockIdx.x >> 4;
    const int loc = blockIdx.x & 15;
    const int s0  = loc * TPB;

    if (tid < TPB) impS[tid] = imp[bb * SEQ + s0 + tid];
    if (tid < DSPACE) biasS[tid] = bias[tid];

    // ---- GEMM1: H[128][64] = X[128][1024] @ W[1024][64] + b ----
    // 16 chunks of 64 d, double-buffered; 512 thr = ks(2b)|tg(4b)|cg(3b)
    const int cg = tid & 7;
    const int tg = (tid >> 3) & 15;
    const int ks = tid >> 7;

    ull acc[4][8];
    #pragma unroll
    for (int u = 0; u < 4; u++)
        #pragma unroll
        for (int j = 0; j < 8; j++) acc[u][j] = 0ull;

    const float4* Xg = (const float4*)(x + (size_t)(bb * SEQ + s0) * DMODEL);
    const float4* Wg = (const float4*)Wm;

    // staging registers
    float4 sxa0, sxb0, sxa1, sxb1, sw0, sw1;
    const int tp0 = tid >> 4,        dq0 = tid & 15;
    const int tp1 = (tid + 512) >> 4, dq1 = (tid + 512) & 15;

    // LDG chunk p into staging regs
    #define G1_LDG(p) do { \
        sxa0 = Xg[(size_t)(2*tp0)   * 256 + (p)*16 + dq0]; \
        sxb0 = Xg[(size_t)(2*tp0+1) * 256 + (p)*16 + dq0]; \
        sxa1 = Xg[(size_t)(2*tp1)   * 256 + (p)*16 + dq1]; \
        sxb1 = Xg[(size_t)(2*tp1+1) * 256 + (p)*16 + dq1]; \
        sw0  = Wg[(size_t)(p)*1024 + tid]; \
        sw1  = Wg[(size_t)(p)*1024 + tid + 512]; \
    } while(0)
    // STS staging regs into buffer (slot = dq + 16c holds d = dq*4+c)
    #define G1_STS(BX, BW) do { \
        { ull* dst = (BX) + (size_t)tp0 * XSP_STRIDE + dq0; \
          dst[0]  = d_pack(sxa0.x, sxb0.x); dst[16] = d_pack(sxa0.y, sxb0.y); \
          dst[32] = d_pack(sxa0.z, sxb0.z); dst[48] = d_pack(sxa0.w, sxb0.w); } \
        { ull* dst = (BX) + (size_t)tp1 * XSP_STRIDE + dq1; \
          dst[0]  = d_pack(sxa1.x, sxb1.x); dst[16] = d_pack(sxa1.y, sxb1.y); \
          dst[32] = d_pack(sxa1.z, sxb1.z); dst[48] = d_pack(sxa1.w, sxb1.w); } \
        ((float4*)(BW))[tid]       = sw0; \
        ((float4*)(BW))[tid + 512] = sw1; \
    } while(0)

    G1_LDG(0);
    G1_STS(bxA, bwA);
    __syncthreads();
    #pragma unroll 2
    for (int p = 0; p < 16; p++) {
        const bool even = ((p & 1) == 0);
        if (p < 15) G1_LDG(p + 1);
        g1_compute(even ? bxA : bxB, even ? bwA : bwB, cg, tg, ks, acc);
        __syncthreads();
        if (p < 15) {
            G1_STS(even ? bxB : bxA, even ? bwB : bwA);
            __syncthreads();
        }
    }

    // ---- k-split exchange: xbuf[tp][ks][col] (aliases buffers) ----
    #pragma unroll
    for (int u = 0; u < 4; u++) {
        const int tp = tg * 4 + u;
        #pragma unroll
        for (int j = 0; j < 8; j++) {
            int col = (j < 4) ? (cg*4 + j) : (32 + cg*4 + (j-4));
            xbuf[(size_t)tp * 256 + ks * 64 + col] = acc[u][j];
        }
    }
    __syncthreads();
    // reduce 4 partials + bias -> HsP2 dup-packed per token
    #pragma unroll
    for (int k = 0; k < 8; k++) {
        int L = tid * 8 + k;            // 0..4095
        int tp = L >> 6, col = L & 63;
        ull s = d_add2(d_add2(xbuf[(size_t)tp*256 + col],
                              xbuf[(size_t)tp*256 + 64 + col]),
                       d_add2(xbuf[(size_t)tp*256 + 128 + col],
                              xbuf[(size_t)tp*256 + 192 + col]));
        float h0, h1; d_unpack(s, h0, h1);
        float bv = biasS[col];
        HsP2[(size_t)(2*tp)   * HSP2_STRIDE + col] = d_dup(h0 + bv);
        HsP2[(size_t)(2*tp+1) * HSP2_STRIDE + col] = d_dup(h1 + bv);
    }

    // ---- GEMM2 + softmax + routing per slice ----
    do_slice<N_QK, 0>(sm, tid);
    do_slice<N_V,  N_QK>(sm, tid);
    do_slice<N_REL, N_QK + N_V>(sm, tid);
    do_slice<N_VAL, N_QK + N_V + N_REL>(sm, tid);

    for (int i = tid; i < N_TOT; i += NTHREADS)
        g_wpart[blockIdx.x][i] = w_local[i];

    // ---- completion counter: last block of this batch finalizes ----
    int* lastFlag = (int*)(sm + SM_FLAG);
    __threadfence();
    if (tid == 0) {
        int old = atomicAdd(&g_cnt[bb], 1);
        *lastFlag = (old == 15);
    }
    __syncthreads();
    if (!*lastFlag) return;

    // finalize: deterministic sum of the 16 partials, then top-k tasks
    float* sws  = (float*)sm;                 // [928]
    int*   flag = (int*)(sm + 4096);          // [512]
    for (int n = tid; n < N_TOT; n += NTHREADS) {
        float s = 0.0f;
        #pragma unroll
        for (int l = 0; l < 16; l++) s += g_wpart[bb * 16 + l][n];
        sws[n] = s;
    }
    __syncthreads();

    // raw w copies
    for (int i = tid; i < N_QK; i += NTHREADS) out[OFF_WQK + bb * N_QK + i] = sws[i];
    for (int i = tid; i < N_V;  i += NTHREADS) out[OFF_WV  + bb * N_V  + i] = sws[N_QK + i];

    // task 1: qk top-64 indices
    topk_flags<N_QK, K_QK>(sws, flag, tid);
    __syncthreads();
    for (int i = tid; i < N_QK; i += NTHREADS) {
        if (flag[i]) {
            int pos = 0;
            for (int j = 0; j < i; j++) pos += flag[j];
            out[OFF_IDXQK + bb * K_QK + pos] = (float)i;
        }
    }
    __syncthreads();
    // task 2: v top-32 indices
    topk_flags<N_V, K_V>(sws + N_QK, flag, tid);
    __syncthreads();
    for (int i = tid; i < N_V; i += NTHREADS) {
        if (flag[i]) {
            int pos = 0;
            for (int j = 0; j < i; j++) pos += flag[j];
            out[OFF_IDXV + bb * K_V + pos] = (float)i;
        }
    }
    __syncthreads();
    // task 3: rel sparsify top-16 (rw_Q == rw_K)
    topk_flags<N_REL, K_REL>(sws + N_QK + N_V, flag, tid);
    __syncthreads();
    for (int i = tid; i < N_REL; i += NTHREADS) {
        float v = flag[i] ? sws[N_QK + N_V + i] : 0.0f;
        out[OFF_RWQ + bb * N_REL + i] = v;
        out[OFF_RWK + bb * N_REL + i] = v;
    }
    __syncthreads();
    // task 4: val sparsify top-3
    topk_flags<N_VAL, K_VAL>(sws + N_QK + N_V + N_REL, flag, tid);
    __syncthreads();
    for (int i = tid; i < N_VAL; i += NTHREADS)
        out[OFF_VW + bb * N_VAL + i] = flag[i] ? sws[N_QK + N_V + N_REL + i] : 0.0f;
}

extern "C" void kernel_launch(void* const* d_in, const int* in_sizes, int n_in,
                              void* d_out, int out_size) {
    const float* x    = (const float*)d_in[0];
    const float* imp  = (const float*)d_in[1];
    const float* Wm   = (const float*)d_in[2];
    const float* bias = (const float*)d_in[3];
    const float* emb  = (const float*)d_in[4];
    float* out = (float*)d_out;

    cudaFuncSetAttribute(main_kernel, cudaFuncAttributeMaxDynamicSharedMemorySize, SMEM_BYTES);

    prep_kernel<<<N_TOT, 64>>>(emb);
    main_kernel<<<NBLOCKS, NTHREADS, SMEM_BYTES>>>(x, imp, Wm, bias, out);
}

// round 9
// speedup vs baseline: 1.1153x; 1.0697x over previous
#include <cuda_runtime.h>
#include <math.h>

typedef unsigned long long ull;

// Problem constants
#define BATCH   8
#define SEQ     2048
#define DMODEL  1024
#define DSPACE  64
#define N_QK    512
#define N_V     256
#define N_REL   128
#define N_VAL   32
#define N_TOT   928
#define K_QK    64
#define K_V     32
#define K_REL   16
#define K_VAL   3

#define TPB      128
#define NTHREADS 512
#define NBLOCKS  (BATCH * SEQ / TPB)      // 128, 16 per batch

// Output layout (float32, reference return order)
#define OFF_IDXQK 0
#define OFF_IDXV  (OFF_IDXQK + BATCH*K_QK)
#define OFF_RWQ   (OFF_IDXV  + BATCH*K_V)
#define OFF_RWK   (OFF_RWQ   + BATCH*N_REL)
#define OFF_VW    (OFF_RWK   + BATCH*N_REL)
#define OFF_WQK   (OFF_VW    + BATCH*N_VAL)
#define OFF_WV    (OFF_WQK   + BATCH*N_QK)

// Shared memory map (bytes)
// U region [0, 131584):
//   GEMM1: bufXa ull[64tp][65] @0 (33280) | bufWa float[64d][64] @33280 (16384)
//          bufXb @49664 (33280)          | bufWb @82944 (16384)
//   aliased by: xbuf ull[64tp][4ks][64col] (131072)
//   aliased by: embS float[64][<=512] (<=131072)
//   aliased by: per-slice wpart, finalize sws/flag
#define SM_BXA   0
#define SM_BWA   33280
#define SM_BXB   49664
#define SM_BWB   82944
#define SM_HSP   131584     // HsP: ull[64tp][66] token-pair packed H (33792)
#define SM_WL    165376     // w_local float[928]
#define SM_IMP   169088     // impS float[128]
#define SM_PART  169600     // partS float[256]
#define SM_ALPHA 170624     // alphaS float[128]
#define SM_FLAG  171136     // int
#define SM_BIAS  171264     // float[64]
#define SMEM_BYTES 171520

#define XSP_STRIDE 65       // ull (64 slots + pad) for GEMM1 staging buffers
#define HSP_STRIDE 66       // ull

// device scratch (no allocation allowed)
__device__ float g_embT[DSPACE * N_TOT];        // normalized emb transposed [d][n]
__device__ float g_wpart[NBLOCKS][N_TOT];       // per-block partial w
__device__ int   g_cnt[BATCH];                  // completion counters

// ---------------- f32x2 helpers ----------------
__device__ __forceinline__ ull d_pack(float x, float y) {
    ull r; asm("mov.b64 %0, {%1, %2};" : "=l"(r) : "f"(x), "f"(y)); return r;
}
__device__ __forceinline__ ull d_dup(float x) {
    ull r; asm("mov.b64 %0, {%1, %1};" : "=l"(r) : "f"(x)); return r;
}
__device__ __forceinline__ void d_unpack(ull v, float& x, float& y) {
    asm("mov.b64 {%0, %1}, %2;" : "=f"(x), "=f"(y) : "l"(v));
}
__device__ __forceinline__ ull d_fma2(ull a, ull b, ull c) {
    ull d; asm("fma.rn.f32x2 %0, %1, %2, %3;" : "=l"(d) : "l"(a), "l"(b), "l"(c)); return d;
}
__device__ __forceinline__ ull d_add2(ull a, ull b) {
    ull d; asm("add.rn.f32x2 %0, %1, %2;" : "=l"(d) : "l"(a), "l"(b)); return d;
}

// ---------------- prep: normalize emb (transposed) + reset counters ----------------
__global__ void prep_kernel(const float* __restrict__ emb) {
    int r = blockIdx.x;     // neuron 0..927
    int t = threadIdx.x;    // dim 0..63
    if (r == 0 && t < BATCH) g_cnt[t] = 0;
    __shared__ float s[64];
    float v = emb[r * DSPACE + t];
    s[t] = v * v;
    __syncthreads();
    #pragma unroll
    for (int o = 32; o > 0; o >>= 1) {
        if (t < o) s[t] += s[t + o];
        __syncthreads();
    }
    float norm = sqrtf(s[0]);
    g_embT[t * N_TOT + r] = v / norm;
}

// ---------------- GEMM2 + softmax + routed-weight slice (R6 token-pair version) ----------------
template<int N, int LO>
__device__ __forceinline__ void do_slice(char* sm, int tid) {
    float* embS   = (float*)sm;
    ull*   HsP    = (ull*)(sm + SM_HSP);
    float* w_local= (float*)(sm + SM_WL);
    float* impS   = (float*)(sm + SM_IMP);
    float* partS  = (float*)(sm + SM_PART);
    float* alphaS = (float*)(sm + SM_ALPHA);
    float* wpartF = (float*)sm;                       // aliases U after embS reads done

    constexpr int NQ   = N / 8;                          // threads along n
    constexpr int LNQ  = (NQ==64)?6:(NQ==32)?5:(NQ==16)?4:2;
    constexpr int G    = NTHREADS / NQ;                  // q groups
    constexpr int TG   = (G*8 > TPB) ? TPB : G*8;        // tokens per pass
    constexpr int AG   = TG / 8;                         // active q groups
    constexpr int W    = (NQ < 32) ? NQ : 32;            // shuffle width
    constexpr int N4   = N / 4;

    const int nq = tid & (NQ - 1);
    const int q  = tid >> LNQ;
    const bool active = (q < AG);

    __syncthreads();
    for (int i = tid; i < 64 * N4; i += NTHREADS) {
        int d = i / N4, c = i - d * N4;
        ((float4*)embS)[i] = *(const float4*)(g_embT + (size_t)d * N_TOT + LO + c * 4);
    }
    __syncthreads();

    ull wacc2[8];
    #pragma unroll
    for (int j = 0; j < 8; j++) wacc2[j] = 0ull;

    for (int t0 = 0; t0 < TPB; t0 += TG) {
        ull acc[4][8];
        if (active) {
            #pragma unroll
            for (int u = 0; u < 4; u++)
                #pragma unroll
                for (int j = 0; j < 8; j++) acc[u][j] = 0ull;

            const ull* hrow = HsP + (size_t)(t0 / 2 + q * 4) * HSP_STRIDE;
            const float4* eb4 = (const float4*)embS;
            #pragma unroll 4
            for (int d = 0; d < DSPACE; d++) {
                // conflict-free: 16B lane stride; neurons {nq*4..+3} and {N/2+nq*4..+3}
                float4 b0 = eb4[d * N4 + nq];
                float4 b1 = eb4[d * N4 + NQ + nq];
                ull bd[8];
                bd[0]=d_dup(b0.x); bd[1]=d_dup(b0.y); bd[2]=d_dup(b0.z); bd[3]=d_dup(b0.w);
                bd[4]=d_dup(b1.x); bd[5]=d_dup(b1.y); bd[6]=d_dup(b1.z); bd[7]=d_dup(b1.w);
                ull a0 = hrow[d];
                ull a1 = hrow[HSP_STRIDE + d];
                ull a2 = hrow[2*HSP_STRIDE + d];
                ull a3 = hrow[3*HSP_STRIDE + d];
                #pragma unroll
                for (int j = 0; j < 8; j++) {
                    acc[0][j] = d_fma2(a0, bd[j], acc[0][j]);
                    acc[1][j] = d_fma2(a1, bd[j], acc[1][j]);
                    acc[2][j] = d_fma2(a2, bd[j], acc[2][j]);
                    acc[3][j] = d_fma2(a3, bd[j], acc[3][j]);
                }
            }
            // exp in-place (repack into acc) + per-token partial sums
            float ps[8];
            #pragma unroll
            for (int u = 0; u < 4; u++) {
                float sx = 0.0f, sy = 0.0f;
                #pragma unroll
                for (int j = 0; j < 8; j++) {
                    float lo, hi;
                    d_unpack(acc[u][j], lo, hi);
                    float e0 = __expf(lo), e1 = __expf(hi);
                    acc[u][j] = d_pack(e0, e1);
                    sx += e0; sy += e1;
                }
                ps[2*u] = sx; ps[2*u+1] = sy;
            }
            #pragma unroll
            for (int tt = 0; tt < 8; tt++)
                #pragma unroll
                for (int o = W >> 1; o > 0; o >>= 1)
                    ps[tt] += __shfl_xor_sync(0xffffffffu, ps[tt], o);
            if (NQ == 64) {
                if ((tid & 31) == 0) {
                    int half = (tid >> 5) & 1;
                    #pragma unroll
                    for (int tt = 0; tt < 8; tt++) partS[(q*8+tt)*2 + half] = ps[tt];
                }
            } else {
                if (nq == 0) {
                    #pragma unroll
                    for (int tt = 0; tt < 8; tt++) {
                        partS[(q*8+tt)*2]     = ps[tt];
                        partS[(q*8+tt)*2 + 1] = 0.0f;
                    }
                }
            }
        }
        __syncthreads();
        if (tid < TG) alphaS[tid] = impS[t0 + tid] / (partS[2*tid] + partS[2*tid+1]);
        __syncthreads();
        if (active) {
            #pragma unroll
            for (int u = 0; u < 4; u++) {
                ull a2p = d_pack(alphaS[q*8 + 2*u], alphaS[q*8 + 2*u + 1]);
                #pragma unroll
                for (int j = 0; j < 8; j++)
                    wacc2[j] = d_fma2(a2p, acc[u][j], wacc2[j]);
            }
        }
    }
    // deterministic cross-group reduction (wpart aliases U; embS reads all done)
    if (active) {
        #pragma unroll
        for (int j = 0; j < 8; j++) {
            float lo, hi;
            d_unpack(wacc2[j], lo, hi);
            int n = (j < 4) ? (nq*4 + j) : (N/2 + nq*4 + (j-4));
            wpartF[q * N + n] = lo + hi;
        }
    }
    __syncthreads();
    for (int n = tid; n < N; n += NTHREADS) {
        float s = 0.0f;
        #pragma unroll
        for (int g = 0; g < AG; g++) s += wpartF[g * N + n];
        w_local[LO + n] = s;
    }
    __syncthreads();
}

// ---------------- finalize helpers ----------------
template<int NN, int KK>
__device__ __forceinline__ void topk_flags(const float* ws, int* flag, int tid) {
    for (int i = tid; i < NN; i += NTHREADS) {
        float wi = ws[i]; int r = 0;
        #pragma unroll 16
        for (int j = 0; j < NN; j++) {
            float wj = ws[j];
            r += (wj > wi) || (wj == wi && j < i);
        }
        flag[i] = (r < KK) ? 1 : 0;
    }
}

// ---------------- GEMM1 chunk compute (64 d), float4 W + reg dups ----------------
__device__ __forceinline__ void g1_compute(const ull* __restrict__ bx,
                                           const float* __restrict__ bw,
                                           int cg, int tg, int ks, ull acc[4][8]) {
    const ull* xrow = bx + (size_t)(tg * 4) * XSP_STRIDE;
    const float4* Ws4 = (const float4*)bw;
    #pragma unroll 4
    for (int i = 0; i < 16; i++) {
        const int slot = ks * 16 + i;      // holds logical d = i*4 + ks
        const int d    = i * 4 + ks;
        float4 b0 = Ws4[d * 16 + cg];      // cols 4cg..4cg+3
        float4 b1 = Ws4[d * 16 + 8 + cg];  // cols 32+4cg..+3
        ull bd[8];
        bd[0]=d_dup(b0.x); bd[1]=d_dup(b0.y); bd[2]=d_dup(b0.z); bd[3]=d_dup(b0.w);
        bd[4]=d_dup(b1.x); bd[5]=d_dup(b1.y); bd[6]=d_dup(b1.z); bd[7]=d_dup(b1.w);
        ull a0 = xrow[slot];
        ull a1 = xrow[XSP_STRIDE + slot];
        ull a2 = xrow[2*XSP_STRIDE + slot];
        ull a3 = xrow[3*XSP_STRIDE + slot];
        #pragma unroll
        for (int j = 0; j < 8; j++) {
            acc[0][j] = d_fma2(a0, bd[j], acc[0][j]);
            acc[1][j] = d_fma2(a1, bd[j], acc[1][j]);
            acc[2][j] = d_fma2(a2, bd[j], acc[2][j]);
            acc[3][j] = d_fma2(a3, bd[j], acc[3][j]);
        }
    }
}

// ---------------- main fused kernel ----------------
__global__ void __launch_bounds__(NTHREADS, 1)
main_kernel(const float* __restrict__ x, const float* __restrict__ imp,
            const float* __restrict__ Wm, const float* __restrict__ bias,
            float* __restrict__ out)
{
    extern __shared__ char sm[];
    ull*   bxA    = (ull*)(sm + SM_BXA);
    float* bwA    = (float*)(sm + SM_BWA);
    ull*   bxB    = (ull*)(sm + SM_BXB);
    float* bwB    = (float*)(sm + SM_BWB);
    ull*   xbuf   = (ull*)sm;                        // exchange (aliases buffers)
    ull*   HsP    = (ull*)(sm + SM_HSP);
    float* w_local= (float*)(sm + SM_WL);
    float* impS   = (float*)(sm + SM_IMP);
    float* biasS  = (float*)(sm + SM_BIAS);

    const int tid = threadIdx.x;
    const int bb  = blockIdx.x >> 4;
    const int loc = blockIdx.x & 15;
    const int s0  = loc * TPB;

    if (tid < TPB) impS[tid] = imp[bb * SEQ + s0 + tid];
    if (tid < DSPACE) biasS[tid] = bias[tid];

    // ---- GEMM1: H[128][64] = X[128][1024] @ W[1024][64] + b ----
    // 16 chunks of 64 d, double-buffered; 512 thr = ks(2b)|tg(4b)|cg(3b)
    const int cg = tid & 7;
    const int tg = (tid >> 3) & 15;
    const int ks = tid >> 7;

    ull acc[4][8];
    #pragma unroll
    for (int u = 0; u < 4; u++)
        #pragma unroll
        for (int j = 0; j < 8; j++) acc[u][j] = 0ull;

    const float4* Xg = (const float4*)(x + (size_t)(bb * SEQ + s0) * DMODEL);
    const float4* Wg = (const float4*)Wm;

    float4 sxa0, sxb0, sxa1, sxb1, sw0, sw1;
    const int tp0 = tid >> 4,         dq0 = tid & 15;
    const int tp1 = (tid + 512) >> 4, dq1 = (tid + 512) & 15;

    #define G1_LDG(p) do { \
        sxa0 = Xg[(size_t)(2*tp0)   * 256 + (p)*16 + dq0]; \
        sxb0 = Xg[(size_t)(2*tp0+1) * 256 + (p)*16 + dq0]; \
        sxa1 = Xg[(size_t)(2*tp1)   * 256 + (p)*16 + dq1]; \
        sxb1 = Xg[(size_t)(2*tp1+1) * 256 + (p)*16 + dq1]; \
        sw0  = Wg[(size_t)(p)*1024 + tid]; \
        sw1  = Wg[(size_t)(p)*1024 + tid + 512]; \
    } while(0)
    #define G1_STS(BX, BW) do { \
        { ull* dst = (BX) + (size_t)tp0 * XSP_STRIDE + dq0; \
          dst[0]  = d_pack(sxa0.x, sxb0.x); dst[16] = d_pack(sxa0.y, sxb0.y); \
          dst[32] = d_pack(sxa0.z, sxb0.z); dst[48] = d_pack(sxa0.w, sxb0.w); } \
        { ull* dst = (BX) + (size_t)tp1 * XSP_STRIDE + dq1; \
          dst[0]  = d_pack(sxa1.x, sxb1.x); dst[16] = d_pack(sxa1.y, sxb1.y); \
          dst[32] = d_pack(sxa1.z, sxb1.z); dst[48] = d_pack(sxa1.w, sxb1.w); } \
        ((float4*)(BW))[tid]       = sw0; \
        ((float4*)(BW))[tid + 512] = sw1; \
    } while(0)

    G1_LDG(0);
    G1_STS(bxA, bwA);
    __syncthreads();
    #pragma unroll 2
    for (int p = 0; p < 16; p++) {
        const bool even = ((p & 1) == 0);
        if (p < 15) G1_LDG(p + 1);
        g1_compute(even ? bxA : bxB, even ? bwA : bwB, cg, tg, ks, acc);
        __syncthreads();
        if (p < 15) {
            G1_STS(even ? bxB : bxA, even ? bwB : bwA);
            __syncthreads();
        }
    }

    // ---- k-split exchange: xbuf[tp][ks][col] (aliases buffers) ----
    #pragma unroll
    for (int u = 0; u < 4; u++) {
        const int tp = tg * 4 + u;
        #pragma unroll
        for (int j = 0; j < 8; j++) {
            int col = (j < 4) ? (cg*4 + j) : (32 + cg*4 + (j-4));
            xbuf[(size_t)tp * 256 + ks * 64 + col] = acc[u][j];
        }
    }
    __syncthreads();
    // reduce 4 partials + bias -> HsP token-pair packed [64tp][66]
    #pragma unroll
    for (int k = 0; k < 8; k++) {
        int L = tid * 8 + k;            // 0..4095
        int tp = L >> 6, col = L & 63;
        ull s = d_add2(d_add2(xbuf[(size_t)tp*256 + col],
                              xbuf[(size_t)tp*256 + 64 + col]),
                       d_add2(xbuf[(size_t)tp*256 + 128 + col],
                              xbuf[(size_t)tp*256 + 192 + col]));
        HsP[(size_t)tp * HSP_STRIDE + col] = d_add2(s, d_dup(biasS[col]));
    }

    // ---- GEMM2 + softmax + routing per slice ----
    do_slice<N_QK, 0>(sm, tid);
    do_slice<N_V,  N_QK>(sm, tid);
    do_slice<N_REL, N_QK + N_V>(sm, tid);
    do_slice<N_VAL, N_QK + N_V + N_REL>(sm, tid);

    for (int i = tid; i < N_TOT; i += NTHREADS)
        g_wpart[blockIdx.x][i] = w_local[i];

    // ---- completion counter: last block of this batch finalizes ----
    int* lastFlag = (int*)(sm + SM_FLAG);
    __threadfence();
    if (tid == 0) {
        int old = atomicAdd(&g_cnt[bb], 1);
        *lastFlag = (old == 15);
    }
    __syncthreads();
    if (!*lastFlag) return;

    // finalize: deterministic sum of the 16 partials, then top-k tasks
    float* sws  = (float*)sm;                 // [928]
    int*   flag = (int*)(sm + 4096);          // [512]
    for (int n = tid; n < N_TOT; n += NTHREADS) {
        float s = 0.0f;
        #pragma unroll
        for (int l = 0; l < 16; l++) s += g_wpart[bb * 16 + l][n];
        sws[n] = s;
    }
    __syncthreads();

    // raw w copies
    for (int i = tid; i < N_QK; i += NTHREADS) out[OFF_WQK + bb * N_QK + i] = sws[i];
    for (int i = tid; i < N_V;  i += NTHREADS) out[OFF_WV  + bb * N_V  + i] = sws[N_QK + i];

    // task 1: qk top-64 indices
    topk_flags<N_QK, K_QK>(sws, flag, tid);
    __syncthreads();
    for (int i = tid; i < N_QK; i += NTHREADS) {
        if (flag[i]) {
            int pos = 0;
            for (int j = 0; j < i; j++) pos += flag[j];
            out[OFF_IDXQK + bb * K_QK + pos] = (float)i;
        }
    }
    __syncthreads();
    // task 2: v top-32 indices
    topk_flags<N_V, K_V>(sws + N_QK, flag, tid);
    __syncthreads();
    for (int i = tid; i < N_V; i += NTHREADS) {
        if (flag[i]) {
            int pos = 0;
            for (int j = 0; j < i; j++) pos += flag[j];
            out[OFF_IDXV + bb * K_V + pos] = (float)i;
        }
    }
    __syncthreads();
    // task 3: rel sparsify top-16 (rw_Q == rw_K)
    topk_flags<N_REL, K_REL>(sws + N_QK + N_V, flag, tid);
    __syncthreads();
    for (int i = tid; i < N_REL; i += NTHREADS) {
        float v = flag[i] ? sws[N_QK + N_V + i] : 0.0f;
        out[OFF_RWQ + bb * N_REL + i] = v;
        out[OFF_RWK + bb * N_REL + i] = v;
    }
    __syncthreads();
    // task 4: val sparsify top-3
    topk_flags<N_VAL, K_VAL>(sws + N_QK + N_V + N_REL, flag, tid);
    __syncthreads();
    for (int i = tid; i < N_VAL; i += NTHREADS)
        out[OFF_VW + bb * N_VAL + i] = flag[i] ? sws[N_QK + N_V + N_REL + i] : 0.0f;
}

extern "C" void kernel_launch(void* const* d_in, const int* in_sizes, int n_in,
                              void* d_out, int out_size) {
    const float* x    = (const float*)d_in[0];
    const float* imp  = (const float*)d_in[1];
    const float* Wm   = (const float*)d_in[2];
    const float* bias = (const float*)d_in[3];
    const float* emb  = (const float*)d_in[4];
    float* out = (float*)d_out;

    cudaFuncSetAttribute(main_kernel, cudaFuncAttributeMaxDynamicSharedMemorySize, SMEM_BYTES);

    prep_kernel<<<N_TOT, 64>>>(emb);
    main_kernel<<<NBLOCKS, NTHREADS, SMEM_BYTES>>>(x, imp, Wm, bias, out);
}